// round 9
// baseline (speedup 1.0000x reference)
#include <cuda_runtime.h>
#include <cstdint>

// Problem constants
static constexpr int B = 64, T = 512, D = 1024, S = 1024, U = 10;
static constexpr int CT     = 32;            // timesteps per block (= lanes)
static constexpr int NCHK   = T / CT;        // 16 chunks per batch
static constexpr int TILE_D = 256;           // d per tile
static constexpr int NTILE  = D / TILE_D;    // 4
static constexpr int TROW   = 260;           // padded tile row stride (floats), 260 % 32 == 4

// smem float offsets
static constexpr int SM_TILES = 0;                       // 2 * 32*260 = 16640
static constexpr int SM_TILE1 = CT * TROW;               // 8320
static constexpr int SM_PSUM  = 2 * CT * TROW;           // 16640, size 32*85 = 2720
static constexpr int SM_HSUM  = SM_PSUM + CT * 85;       // 19360, size 32*11 = 352
static constexpr int SM_EXV   = SM_HSUM + CT * 11;       // 19712, size 32
static constexpr int SM_RED   = SM_EXV + CT;             // 19744, size 80
static constexpr int SM_U2    = SM_RED + 80;             // 19824, size 10
static constexpr int SM_W2    = SM_U2 + U;               // size 10
static constexpr int SM_B2    = SM_W2 + U;               // size 1
static constexpr int SMEM_FLOATS = SM_B2 + 1;            // 19845
static constexpr int SMEM_BYTES  = SMEM_FLOATS * 4;      // 79380

__constant__ float cWT[U * D];               // W1 front, transposed [u][d]
__device__ float g_WT[U * D];                // staging for transpose
__device__ float g_cpart[B * NCHK * D];      // per-chunk context partials (4 MB)
__device__ float g_e[B * T];                 // exp(e)

typedef unsigned long long ull;

static __device__ __forceinline__ ull pack2(float x, float y) {
    ull r; asm("mov.b64 %0, {%1, %2};" : "=l"(r) : "f"(x), "f"(y)); return r;
}
static __device__ __forceinline__ float2 unpack2(ull v) {
    float2 r; asm("mov.b64 {%0, %1}, %2;" : "=f"(r.x), "=f"(r.y) : "l"(v)); return r;
}
static __device__ __forceinline__ ull fma2(ull a, ull b, ull c) {
    ull d; asm("fma.rn.f32x2 %0, %1, %2, %3;" : "=l"(d) : "l"(a), "l"(b), "l"(c)); return d;
}
static __device__ __forceinline__ float fast_tanh(float x) {
    float ex = __expf(2.0f * x);
    return 1.0f - __fdividef(2.0f, ex + 1.0f);
}

// issue cp.async for one 32t x 256d tile (2048 x 16B, 8 per thread, coalesced)
static __device__ __forceinline__ void load_tile(float* dstf, const float* src,
                                                 int jt, int tid) {
    unsigned dst = (unsigned)__cvta_generic_to_shared(dstf);
    const float* g = src + jt * TILE_D;
#pragma unroll
    for (int k = 0; k < 8; k++) {
        int idx = tid + k * 256;
        int t = idx >> 6, dq = idx & 63;
        unsigned ds = dst + (unsigned)(t * TROW + dq * 4) * 4u;
        const float* gp = g + (size_t)t * D + dq * 4;
        asm volatile("cp.async.ca.shared.global [%0], [%1], 16;" :: "r"(ds), "l"(gp));
    }
}

// ---------- transpose W1 front half into g_WT[u][d] ----------
__global__ void kprep(const float* __restrict__ W1) {
    int u = blockIdx.x >> 2, seg = blockIdx.x & 3;
    int d = seg * 256 + threadIdx.x;
    g_WT[u * D + d] = W1[(size_t)d * U + u];
}

// ---------- K1: lane<->t fused kernel ----------
// grid (NCHK, B), 256 threads = 8 warps. Lane owns timestep t0+lane.
// Warp w owns d-slice [w*32, w*32+32) within each tile for the e-phase,
// and d-slice [w*128, w*128+128) for the context phase.
__global__ void __launch_bounds__(256, 2)
k1_main(const float* __restrict__ a,  const float* __restrict__ sp,
        const float* __restrict__ W1, const float* __restrict__ W2v,
        const float* __restrict__ b1, const float* __restrict__ b2) {
    const int ch = blockIdx.x, b = blockIdx.y;
    const int tid = threadIdx.x, w = tid >> 5, lane = tid & 31;
    const int t0 = ch * CT;

    extern __shared__ float sm[];
    float* tiles = sm + SM_TILES;
    float* psum  = sm + SM_PSUM;
    float* hsum  = sm + SM_HSUM;
    float* exv   = sm + SM_EXV;
    float* red   = sm + SM_RED;
    float* u2s   = sm + SM_U2;
    float* w2s   = sm + SM_W2;
    float* b2s   = sm + SM_B2;

    const float* abase = a + ((size_t)(b * T + t0)) * D;

    // prologue: tiles 0 and 1 in flight
    load_tile(tiles,            abase, 0, tid);
    asm volatile("cp.async.commit_group;" ::: "memory");
    load_tile(tiles + SM_TILE1, abase, 1, tid);
    asm volatile("cp.async.commit_group;" ::: "memory");

    // ---- phase 0: u2 partials (s_prev @ W1 back half), hidden behind cp.async ----
    {
        const int d0 = 4 * tid;
        float4 s4 = *reinterpret_cast<const float4*>(sp + (size_t)b * S + d0);
        float sj[4] = {s4.x, s4.y, s4.z, s4.w};
        float p[U];
#pragma unroll
        for (int u = 0; u < U; u++) p[u] = 0.0f;
#pragma unroll
        for (int j = 0; j < 4; j++) {
            const float2* r = reinterpret_cast<const float2*>(W1 + (size_t)(D + d0 + j) * U);
#pragma unroll
            for (int k = 0; k < 5; k++) {
                float2 v = r[k];
                p[2 * k]     += sj[j] * v.x;
                p[2 * k + 1] += sj[j] * v.y;
            }
        }
#pragma unroll
        for (int off = 16; off; off >>= 1)
#pragma unroll
            for (int u = 0; u < U; u++) p[u] += __shfl_xor_sync(0xffffffffu, p[u], off);
        if (lane == 0) {
#pragma unroll
            for (int u = 0; u < U; u++) red[w * U + u] = p[u];
        }
    }
    __syncthreads();
    if (tid < U) {
        float s = 0.0f;
#pragma unroll
        for (int k = 0; k < 8; k++) s += red[k * U + tid];
        u2s[tid] = s + b1[tid];
        w2s[tid] = W2v[tid];
    }
    if (tid == 0) b2s[0] = b2[0];

    // ---- e-phase: tiles, lane<->t, uniform constant weights ----
    ull acc[U];
#pragma unroll
    for (int u = 0; u < U; u++) acc[u] = 0ull;   // packed (even-d, odd-d) partial

#pragma unroll
    for (int j = 0; j < NTILE; j++) {
        if (j < NTILE - 1) asm volatile("cp.async.wait_group 1;" ::: "memory");
        else               asm volatile("cp.async.wait_group 0;" ::: "memory");
        __syncthreads();   // tile j visible to all (also publishes u2s on j==0)

        const float* tl = tiles + (j & 1) * SM_TILE1 + lane * TROW + w * 32;
        const int dg = j * TILE_D + w * 32;
#pragma unroll
        for (int i = 0; i < 8; i++) {
            float4 av = *reinterpret_cast<const float4*>(tl + i * 4);
            ull a01 = pack2(av.x, av.y), a23 = pack2(av.z, av.w);
#pragma unroll
            for (int u = 0; u < U; u++) {
                float4 w4 = *reinterpret_cast<const float4*>(&cWT[u * D + dg + i * 4]);
                acc[u] = fma2(a01, pack2(w4.x, w4.y),
                         fma2(a23, pack2(w4.z, w4.w), acc[u]));
            }
        }
        __syncthreads();   // all done reading buffer (j&1)
        if (j + 2 < NTILE) {
            load_tile(tiles + (j & 1) * SM_TILE1, abase, j + 2, tid);
            asm volatile("cp.async.commit_group;" ::: "memory");
        }
    }

    // ---- finalize e: cross-warp psum (odd strides, conflict-free) ----
#pragma unroll
    for (int u = 0; u < U; u++) {
        float2 f = unpack2(acc[u]);
        psum[lane * 85 + w * 10 + u] = f.x + f.y;
    }
    __syncthreads();
    {
        int t = tid & 31, u = tid >> 5;        // u in 0..7
        float s = u2s[u];
#pragma unroll
        for (int k = 0; k < 8; k++) s += psum[t * 85 + k * 10 + u];
        hsum[t * 11 + u] = w2s[u] * fast_tanh(s);
        if (tid < 64) {                        // u = 8, 9
            int u2i = 8 + (tid >> 5);
            float s2 = u2s[u2i];
#pragma unroll
            for (int k = 0; k < 8; k++) s2 += psum[t * 85 + k * 10 + u2i];
            hsum[t * 11 + u2i] = w2s[u2i] * fast_tanh(s2);
        }
    }
    __syncthreads();
    if (tid < CT) {
        float e = b2s[0];
#pragma unroll
        for (int u = 0; u < U; u++) e += hsum[tid * 11 + u];
        float ex = __expf(fmaxf(e, 0.0f));     // max-free: e in [0, ~3]
        exv[tid] = ex;
        g_e[b * T + t0 + tid] = ex;
    }
    __syncthreads();

    // ---- context phase: warp w owns d [w*128, w*128+128), re-read a (L1/L2 hot) ----
    {
        const float* ap = abase + w * 128 + lane * 4;
        ull c0 = 0ull, c1 = 0ull;
#pragma unroll 8
        for (int t = 0; t < CT; t++) {
            float4 v = *reinterpret_cast<const float4*>(ap + (size_t)t * D);
            float ext = exv[t];                // broadcast LDS
            ull E = pack2(ext, ext);
            c0 = fma2(E, pack2(v.x, v.y), c0);
            c1 = fma2(E, pack2(v.z, v.w), c1);
        }
        float2 lo = unpack2(c0), hi = unpack2(c1);
        *reinterpret_cast<float4*>(
            &g_cpart[((size_t)(b * NCHK + ch)) * D + w * 128 + lane * 4]) =
            make_float4(lo.x, lo.y, hi.x, hi.y);
    }
}

// ---------- K2: combine 16 chunk partials, normalize, write outputs ----------
__global__ void k2_combine(float* __restrict__ out, int scoreOff, int doScores) {
    int bq = blockIdx.x;
    int b = bq >> 2, dq = bq & 3;
    int tid = threadIdx.x;
    __shared__ float redz[8];
    __shared__ float zsh;

    float e0 = g_e[b * T + tid];
    float e1 = g_e[b * T + 256 + tid];
    float s = e0 + e1;
#pragma unroll
    for (int off = 16; off; off >>= 1) s += __shfl_xor_sync(0xffffffffu, s, off);
    if ((tid & 31) == 0) redz[tid >> 5] = s;
    __syncthreads();
    if (tid == 0) {
        float z = 0.0f;
#pragma unroll
        for (int k = 0; k < 8; k++) z += redz[k];
        zsh = 1.0f / z;              // z >= 512 (e >= 0), safe
    }
    __syncthreads();
    float invZ = zsh;

    if (dq == 0 && doScores) {
        out[scoreOff + b * T + tid]       = e0 * invZ;
        out[scoreOff + b * T + 256 + tid] = e1 * invZ;
    }

    int d = dq * 256 + tid;
    float c = 0.0f;
#pragma unroll
    for (int chn = 0; chn < NCHK; chn++)
        c += g_cpart[((size_t)(b * NCHK + chn)) * D + d];
    out[(size_t)b * D + d] = c * invZ;
}

extern "C" void kernel_launch(void* const* d_in, const int* in_sizes, int n_in,
                              void* d_out, int out_size) {
    const float* a   = (const float*)d_in[0];   // [B,T,D]
    const float* sp  = (const float*)d_in[1];   // [B,S]
    const float* W1  = (const float*)d_in[2];   // [D+S, 10]
    const float* b1  = (const float*)d_in[3];   // [10]
    const float* W2  = (const float*)d_in[4];   // [10, 1]
    const float* b2  = (const float*)d_in[5];   // [1]
    float* out = (float*)d_out;

    int scoreOff = B * D;
    int doScores = (out_size >= B * D + B * T) ? 1 : 0;

    cudaFuncSetAttribute(k1_main, cudaFuncAttributeMaxDynamicSharedMemorySize, SMEM_BYTES);

    kprep<<<40, 256>>>(W1);

    void *cw = nullptr, *gw = nullptr;
    cudaGetSymbolAddress(&cw, cWT);
    cudaGetSymbolAddress(&gw, g_WT);
    cudaMemcpyAsync(cw, gw, U * D * sizeof(float), cudaMemcpyDeviceToDevice, 0);

    k1_main<<<dim3(NCHK, B), 256, SMEM_BYTES>>>(a, sp, W1, W2, b1, b2);
    k2_combine<<<4 * B, 256>>>(out, scoreOff, doScores);
}

// round 10
// speedup vs baseline: 6.9534x; 6.9534x over previous
#include <cuda_runtime.h>
#include <cstdint>

// Problem constants
static constexpr int B = 64, T = 512, D = 1024, S = 1024, U = 10;
static constexpr int CT     = 32;            // timesteps per block (= lanes)
static constexpr int NCHK   = T / CT;        // 16 chunks per batch
static constexpr int TILE_D = 256;           // d per tile
static constexpr int NTILE  = D / TILE_D;    // 4
static constexpr int TROW   = 260;           // padded a-tile row stride (floats)

// smem float offsets
static constexpr int SM_TILES = 0;                       // a-tiles: 2 * 32*260 = 16640
static constexpr int SM_TILE1 = CT * TROW;               // 8320
static constexpr int SM_WST   = 2 * CT * TROW;           // w-tiles: 2 * 10*256 = 5120
static constexpr int SM_WST1  = U * TILE_D;              // 2560
static constexpr int SM_PSUM  = SM_WST + 2 * SM_WST1;    // 21760, size 32*85 = 2720
static constexpr int SM_HSUM  = SM_PSUM + CT * 85;       // size 32*11 = 352
static constexpr int SM_EXV   = SM_HSUM + CT * 11;       // size 32
static constexpr int SM_RED   = SM_EXV + CT;             // size 80
static constexpr int SM_U2    = SM_RED + 80;             // size 10
static constexpr int SM_W2    = SM_U2 + U;               // size 10
static constexpr int SM_B2    = SM_W2 + U;               // size 1
static constexpr int SMEM_FLOATS = SM_B2 + 1;
static constexpr int SMEM_BYTES  = SMEM_FLOATS * 4;      // ~99.9 KB

__device__ float g_WT[U * D];                // W1 front, transposed [u][d]
__device__ float g_cpart[B * NCHK * D];      // per-chunk context partials (4 MB)
__device__ float g_e[B * T];                 // exp(e)

typedef unsigned long long ull;

static __device__ __forceinline__ ull pack2(float x, float y) {
    ull r; asm("mov.b64 %0, {%1, %2};" : "=l"(r) : "f"(x), "f"(y)); return r;
}
static __device__ __forceinline__ float2 unpack2(ull v) {
    float2 r; asm("mov.b64 {%0, %1}, %2;" : "=f"(r.x), "=f"(r.y) : "l"(v)); return r;
}
static __device__ __forceinline__ ull fma2(ull a, ull b, ull c) {
    ull d; asm("fma.rn.f32x2 %0, %1, %2, %3;" : "=l"(d) : "l"(a), "l"(b), "l"(c)); return d;
}
static __device__ __forceinline__ float fast_tanh(float x) {
    float ex = __expf(2.0f * x);
    return 1.0f - __fdividef(2.0f, ex + 1.0f);
}

// cp.async one 32t x 256d a-tile (2048 x 16B, 8 per thread, coalesced rows)
static __device__ __forceinline__ void load_atile(float* dstf, const float* src,
                                                  int jt, int tid) {
    unsigned dst = (unsigned)__cvta_generic_to_shared(dstf);
    const float* g = src + jt * TILE_D;
#pragma unroll
    for (int k = 0; k < 8; k++) {
        int idx = tid + k * 256;
        int t = idx >> 6, dq = idx & 63;
        unsigned ds = dst + (unsigned)(t * TROW + dq * 4) * 4u;
        const float* gp = g + (size_t)t * D + dq * 4;
        asm volatile("cp.async.ca.shared.global [%0], [%1], 16;" :: "r"(ds), "l"(gp));
    }
}
// cp.async one 10u x 256d weight tile (640 x 16B)
static __device__ __forceinline__ void load_wtile(float* dstf, int jt, int tid) {
    unsigned dst = (unsigned)__cvta_generic_to_shared(dstf);
#pragma unroll
    for (int k = 0; k < 3; k++) {
        int idx = tid + k * 256;
        if (idx < U * 64) {
            int u = idx >> 6, c4 = idx & 63;
            unsigned ds = dst + (unsigned)(u * TILE_D + c4 * 4) * 4u;
            const float* gp = g_WT + (size_t)u * D + jt * TILE_D + c4 * 4;
            asm volatile("cp.async.ca.shared.global [%0], [%1], 16;" :: "r"(ds), "l"(gp));
        }
    }
}

// ---------- transpose W1 front half into g_WT[u][d] ----------
__global__ void kprep(const float* __restrict__ W1) {
    int u = blockIdx.x >> 2, seg = blockIdx.x & 3;
    int d = seg * 256 + threadIdx.x;
    g_WT[u * D + d] = W1[(size_t)d * U + u];
}

// ---------- K1: lane<->t fused kernel; weights via smem broadcast LDS ----------
// grid (NCHK, B), 256 threads = 8 warps. Lane owns timestep t0+lane.
// Warp w covers d-slice [w*32, w*32+32) per tile (e-phase) / [w*128,...) (ctx).
__global__ void __launch_bounds__(256, 2)
k1_main(const float* __restrict__ a,  const float* __restrict__ sp,
        const float* __restrict__ W1, const float* __restrict__ W2v,
        const float* __restrict__ b1, const float* __restrict__ b2) {
    const int ch = blockIdx.x, b = blockIdx.y;
    const int tid = threadIdx.x, w = tid >> 5, lane = tid & 31;
    const int t0 = ch * CT;

    extern __shared__ float sm[];
    float* tiles = sm + SM_TILES;
    float* wst   = sm + SM_WST;
    float* psum  = sm + SM_PSUM;
    float* hsum  = sm + SM_HSUM;
    float* exv   = sm + SM_EXV;
    float* red   = sm + SM_RED;
    float* u2s   = sm + SM_U2;
    float* w2s   = sm + SM_W2;
    float* b2s   = sm + SM_B2;

    const float* abase = a + ((size_t)(b * T + t0)) * D;

    // prologue: tiles 0 and 1 (a + weights) in flight
    load_atile(tiles,            abase, 0, tid);
    load_wtile(wst,              0, tid);
    asm volatile("cp.async.commit_group;" ::: "memory");
    load_atile(tiles + SM_TILE1, abase, 1, tid);
    load_wtile(wst + SM_WST1,    1, tid);
    asm volatile("cp.async.commit_group;" ::: "memory");

    // ---- phase 0: u2 partials (s_prev @ W1 back half), hidden behind cp.async ----
    {
        const int d0 = 4 * tid;
        float4 s4 = *reinterpret_cast<const float4*>(sp + (size_t)b * S + d0);
        float sj[4] = {s4.x, s4.y, s4.z, s4.w};
        float p[U];
#pragma unroll
        for (int u = 0; u < U; u++) p[u] = 0.0f;
#pragma unroll
        for (int j = 0; j < 4; j++) {
            const float2* r = reinterpret_cast<const float2*>(W1 + (size_t)(D + d0 + j) * U);
#pragma unroll
            for (int k = 0; k < 5; k++) {
                float2 v = r[k];
                p[2 * k]     += sj[j] * v.x;
                p[2 * k + 1] += sj[j] * v.y;
            }
        }
#pragma unroll
        for (int off = 16; off; off >>= 1)
#pragma unroll
            for (int u = 0; u < U; u++) p[u] += __shfl_xor_sync(0xffffffffu, p[u], off);
        if (lane == 0) {
#pragma unroll
            for (int u = 0; u < U; u++) red[w * U + u] = p[u];
        }
    }
    __syncthreads();
    if (tid < U) {
        float s = 0.0f;
#pragma unroll
        for (int k = 0; k < 8; k++) s += red[k * U + tid];
        u2s[tid] = s + b1[tid];
        w2s[tid] = W2v[tid];
    }
    if (tid == 0) b2s[0] = b2[0];

    // ---- e-phase: lane<->t, warp-uniform broadcast weight reads ----
    ull acc[U];
#pragma unroll
    for (int u = 0; u < U; u++) acc[u] = 0ull;   // packed (even-d, odd-d) partials

#pragma unroll
    for (int j = 0; j < NTILE; j++) {
        if (j < NTILE - 1) asm volatile("cp.async.wait_group 1;" ::: "memory");
        else               asm volatile("cp.async.wait_group 0;" ::: "memory");
        __syncthreads();   // tile j visible (also publishes u2s/w2s on j==0)

        const float* tl = tiles + (j & 1) * SM_TILE1 + lane * TROW + w * 32;
        const float* wb = wst + (j & 1) * SM_WST1 + w * 32;
#pragma unroll
        for (int i = 0; i < 8; i++) {
            float4 av = *reinterpret_cast<const float4*>(tl + i * 4);
            ull a01 = pack2(av.x, av.y), a23 = pack2(av.z, av.w);
#pragma unroll
            for (int u = 0; u < U; u++) {
                // warp-uniform address -> broadcast LDS.128 (16B crossbar total)
                float4 w4 = *reinterpret_cast<const float4*>(wb + u * TILE_D + i * 4);
                acc[u] = fma2(a01, pack2(w4.x, w4.y),
                         fma2(a23, pack2(w4.z, w4.w), acc[u]));
            }
        }
        __syncthreads();   // all warps done reading buffer (j&1)
        if (j + 2 < NTILE) {
            load_atile(tiles + (j & 1) * SM_TILE1, abase, j + 2, tid);
            load_wtile(wst + (j & 1) * SM_WST1,    j + 2, tid);
            asm volatile("cp.async.commit_group;" ::: "memory");
        }
    }

    // ---- finalize e: cross-warp psum (odd strides, conflict-free) ----
#pragma unroll
    for (int u = 0; u < U; u++) {
        float2 f = unpack2(acc[u]);
        psum[lane * 85 + w * 10 + u] = f.x + f.y;
    }
    __syncthreads();
    {
        int t = tid & 31, u = tid >> 5;        // u in 0..7
        float s = u2s[u];
#pragma unroll
        for (int k = 0; k < 8; k++) s += psum[t * 85 + k * 10 + u];
        hsum[t * 11 + u] = w2s[u] * fast_tanh(s);
        if (tid < 64) {                        // u = 8, 9
            int u2i = 8 + (tid >> 5);
            float s2 = u2s[u2i];
#pragma unroll
            for (int k = 0; k < 8; k++) s2 += psum[t * 85 + k * 10 + u2i];
            hsum[t * 11 + u2i] = w2s[u2i] * fast_tanh(s2);
        }
    }
    __syncthreads();
    if (tid < CT) {
        float e = b2s[0];
#pragma unroll
        for (int u = 0; u < U; u++) e += hsum[tid * 11 + u];
        float ex = __expf(fmaxf(e, 0.0f));     // max-free: e in [0, ~3]
        exv[tid] = ex;
        g_e[b * T + t0 + tid] = ex;
    }
    __syncthreads();

    // ---- context: warp w owns d [w*128, w*128+128), re-read a (L2-hot) ----
    {
        const float* ap = abase + w * 128 + lane * 4;
        ull c0 = 0ull, c1 = 0ull;
#pragma unroll 8
        for (int t = 0; t < CT; t++) {
            float4 v = *reinterpret_cast<const float4*>(ap + (size_t)t * D);
            float ext = exv[t];                // broadcast LDS
            ull E = pack2(ext, ext);
            c0 = fma2(E, pack2(v.x, v.y), c0);
            c1 = fma2(E, pack2(v.z, v.w), c1);
        }
        float2 lo = unpack2(c0), hi = unpack2(c1);
        *reinterpret_cast<float4*>(
            &g_cpart[((size_t)(b * NCHK + ch)) * D + w * 128 + lane * 4]) =
            make_float4(lo.x, lo.y, hi.x, hi.y);
    }
}

// ---------- K2: combine 16 chunk partials, normalize, write outputs ----------
__global__ void k2_combine(float* __restrict__ out, int scoreOff, int doScores) {
    int bq = blockIdx.x;
    int b = bq >> 2, dq = bq & 3;
    int tid = threadIdx.x;
    __shared__ float redz[8];
    __shared__ float zsh;

    float e0 = g_e[b * T + tid];
    float e1 = g_e[b * T + 256 + tid];
    float s = e0 + e1;
#pragma unroll
    for (int off = 16; off; off >>= 1) s += __shfl_xor_sync(0xffffffffu, s, off);
    if ((tid & 31) == 0) redz[tid >> 5] = s;
    __syncthreads();
    if (tid == 0) {
        float z = 0.0f;
#pragma unroll
        for (int k = 0; k < 8; k++) z += redz[k];
        zsh = 1.0f / z;              // z >= 512 (e >= 0), safe
    }
    __syncthreads();
    float invZ = zsh;

    if (dq == 0 && doScores) {
        out[scoreOff + b * T + tid]       = e0 * invZ;
        out[scoreOff + b * T + 256 + tid] = e1 * invZ;
    }

    int d = dq * 256 + tid;
    float c = 0.0f;
#pragma unroll
    for (int chn = 0; chn < NCHK; chn++)
        c += g_cpart[((size_t)(b * NCHK + chn)) * D + d];
    out[(size_t)b * D + d] = c * invZ;
}

extern "C" void kernel_launch(void* const* d_in, const int* in_sizes, int n_in,
                              void* d_out, int out_size) {
    const float* a   = (const float*)d_in[0];   // [B,T,D]
    const float* sp  = (const float*)d_in[1];   // [B,S]
    const float* W1  = (const float*)d_in[2];   // [D+S, 10]
    const float* b1  = (const float*)d_in[3];   // [10]
    const float* W2  = (const float*)d_in[4];   // [10, 1]
    const float* b2  = (const float*)d_in[5];   // [1]
    float* out = (float*)d_out;

    int scoreOff = B * D;
    int doScores = (out_size >= B * D + B * T) ? 1 : 0;

    cudaFuncSetAttribute(k1_main, cudaFuncAttributeMaxDynamicSharedMemorySize, SMEM_BYTES);

    kprep<<<40, 256>>>(W1);
    k1_main<<<dim3(NCHK, B), 256, SMEM_BYTES>>>(a, sp, W1, W2, b1, b2);
    k2_combine<<<4 * B, 256>>>(out, scoreOff, doScores);
}